// round 11
// baseline (speedup 1.0000x reference)
#include <cuda_runtime.h>
#include <math.h>

#define BATCH 1024
#define TT    128
#define HID   256
#define KTOT  512      // [x|h] concat K (layer-1 path)
#define KC    32       // K chunk in SMEM
#define BT    128      // batch tile per block
#define NHT   16       // h indices per block (=> 64 gate cols, gate-minor)

// ---------------- persistent device scratch (allocation-free) ----------------
__device__ __align__(16) float g_xT[(size_t)TT * HID * BATCH];   // [t][k][b], relu applied
__device__ __align__(16) float g_hT[2][2][HID * BATCH];          // [layer][parity][h][b]
__device__ __align__(16) float g_c[2][HID * BATCH];              // [layer][h][b]  (k-major like h)
__device__ __align__(16) float g_wP[2][(size_t)NHT * KTOT * 64]; // [layer][ht][k][col], col=jj*4+g
__device__ __align__(16) float g_bC[2][4 * HID];                 // combined bias [g][h]
__device__ __align__(16) float g_gPre[(size_t)TT * HID * BATCH * 4]; // [t][hh][b][4gates], bias folded

__device__ __forceinline__ float sigmoidf_(float v) { return 1.0f / (1.0f + expf(-v)); }

__device__ __forceinline__ void cp_async16(void* smem_dst, const void* gsrc) {
    unsigned sa = (unsigned)__cvta_generic_to_shared(smem_dst);
    asm volatile("cp.async.cg.shared.global [%0], [%1], 16;\n" :: "r"(sa), "l"(gsrc));
}
#define CP_COMMIT() asm volatile("cp.async.commit_group;\n" ::: "memory")
#define CP_WAIT0()  asm volatile("cp.async.wait_group 0;\n" ::: "memory")

// ---------------- prep kernels (run inside the graph every replay) ----------------
__global__ void init_states_kernel() {
    int i = blockIdx.x * blockDim.x + threadIdx.x;
    if (i < BATCH * HID) {
        g_hT[0][0][i] = 0.0f; g_hT[0][1][i] = 0.0f;
        g_hT[1][0][i] = 0.0f; g_hT[1][1][i] = 0.0f;
        g_c[0][i] = 0.0f;     g_c[1][i] = 0.0f;
    }
}

// xT[t][k][b] = relu(x[b][t][k])
__global__ void prep_x_kernel(const float* __restrict__ x) {
    __shared__ float tile[32][33];
    int t  = blockIdx.z;
    int b0 = blockIdx.x * 32;
    int k0 = blockIdx.y * 32;
    int tx = threadIdx.x, ty = threadIdx.y;          // (32, 8)
#pragma unroll
    for (int r = ty; r < 32; r += 8)
        tile[r][tx] = fmaxf(x[((size_t)(b0 + r) * TT + t) * HID + k0 + tx], 0.0f);
    __syncthreads();
#pragma unroll
    for (int r = ty; r < 32; r += 8)
        g_xT[((size_t)t * HID + k0 + r) * BATCH + b0 + tx] = tile[tx][r];
}

// wP[ht][k][col] with col = jj*4 + g,  j = g*HID + ht*16 + jj;  k<256 -> w_ih else w_hh
__global__ void prep_w_kernel(const float* __restrict__ w_ih,
                              const float* __restrict__ w_hh,
                              const float* __restrict__ b_ih,
                              const float* __restrict__ b_hh,
                              int layer) {
    int idx = blockIdx.x * blockDim.x + threadIdx.x;     // [0, 16*512*64)
    if (idx < NHT * KTOT * 64) {
        int col = idx & 63;
        int k   = (idx >> 6) & (KTOT - 1);
        int ht  = idx >> 15;
        int g   = col & 3;
        int jj  = col >> 2;
        int j   = g * HID + ht * 16 + jj;
        float v = (k < HID) ? w_ih[(size_t)j * HID + k] : w_hh[(size_t)j * HID + (k - HID)];
        g_wP[layer][idx] = v;
    }
    if (idx < 4 * HID) g_bC[layer][idx] = b_ih[idx] + b_hh[idx];
}

// ---------------- shared GEMM tile machinery ----------------
// Block tile: 128 batches x 16 h-indices (64 gate cols, gate-minor). 256 threads.
// Thread (tx, ty): tx = h-index-local [0,16), ty = batch group [0,16) of 8 rows.
__device__ __forceinline__ void gemm_chunk(const float As[KC][BT], const float Bs[KC][64],
                                           int tx, int ty, float acc[8][4]) {
#pragma unroll 8
    for (int kk = 0; kk < KC; kk++) {
        float4 a0  = *(const float4*)&As[kk][ty * 8];      // broadcast across tx
        float4 a1f = *(const float4*)&As[kk][ty * 8 + 4];
        float4 b   = *(const float4*)&Bs[kk][tx * 4];      // 4 gates of one jj
        acc[0][0] += a0.x * b.x; acc[0][1] += a0.x * b.y; acc[0][2] += a0.x * b.z; acc[0][3] += a0.x * b.w;
        acc[1][0] += a0.y * b.x; acc[1][1] += a0.y * b.y; acc[1][2] += a0.y * b.z; acc[1][3] += a0.y * b.w;
        acc[2][0] += a0.z * b.x; acc[2][1] += a0.z * b.y; acc[2][2] += a0.z * b.z; acc[2][3] += a0.z * b.w;
        acc[3][0] += a0.w * b.x; acc[3][1] += a0.w * b.y; acc[3][2] += a0.w * b.z; acc[3][3] += a0.w * b.w;
        acc[4][0] += a1f.x * b.x; acc[4][1] += a1f.x * b.y; acc[4][2] += a1f.x * b.z; acc[4][3] += a1f.x * b.w;
        acc[5][0] += a1f.y * b.x; acc[5][1] += a1f.y * b.y; acc[5][2] += a1f.y * b.z; acc[5][3] += a1f.y * b.w;
        acc[6][0] += a1f.z * b.x; acc[6][1] += a1f.z * b.y; acc[6][2] += a1f.z * b.z; acc[6][3] += a1f.z * b.w;
        acc[7][0] += a1f.w * b.x; acc[7][1] += a1f.w * b.y; acc[7][2] += a1f.w * b.z; acc[7][3] += a1f.w * b.w;
    }
}

__device__ __forceinline__ void prefetch_tiles(float As[KC][BT], float Bs[KC][64],
                                               const float* asrc, const float* wsrc_c,
                                               int tid, int bt0) {
#pragma unroll
    for (int s = 0; s < 4; s++) {              // A: 32x128 = 1024 float4
        int idx = tid + s * 256;
        int k = idx >> 5, f = idx & 31;
        cp_async16(&As[k][f * 4], asrc + (size_t)k * BATCH + bt0 + f * 4);
    }
#pragma unroll
    for (int s = 0; s < 2; s++) {              // B: 32x64 = 512 float4
        int idx = tid + s * 256;
        int k = idx >> 4, f = idx & 15;
        cp_async16(&Bs[k][f * 4], wsrc_c + (size_t)k * 64 + f * 4);
    }
    CP_COMMIT();
}

// ---------------- parallel input GEMM: gPre[t][hh][b][g] = relu(x)@W_ih0^T + bias0 ----------------
__global__ void __launch_bounds__(256, 2)
precompute_gates() {
    __shared__ __align__(16) float As[2][KC][BT];
    __shared__ __align__(16) float Bs[2][KC][64];

    const int tid = threadIdx.x;
    const int tx  = tid & 15;
    const int ty  = tid >> 4;
    const int bt0 = blockIdx.x * BT;
    const int t   = blockIdx.z;
    const float* a1   = g_xT + (size_t)t * HID * BATCH;
    const float* wsrc = g_wP[0] + (size_t)blockIdx.y * KTOT * 64;   // k in [0,256): w_ih part

    const int hh = blockIdx.y * NHT + tx;
    float acc[8][4];
#pragma unroll
    for (int v = 0; v < 8; v++) {
        acc[v][0] = g_bC[0][0 * HID + hh];
        acc[v][1] = g_bC[0][1 * HID + hh];
        acc[v][2] = g_bC[0][2 * HID + hh];
        acc[v][3] = g_bC[0][3 * HID + hh];
    }

    const int NCH = HID / KC;   // 8 chunks, input half only
    prefetch_tiles(As[0], Bs[0], a1, wsrc, tid, bt0);
    int buf = 0;
    for (int c = 0; c < NCH; c++) {
        CP_WAIT0();
        __syncthreads();
        if (c + 1 < NCH)
            prefetch_tiles(As[buf ^ 1], Bs[buf ^ 1],
                           a1 + (size_t)(c + 1) * KC * BATCH,
                           wsrc + (size_t)(c + 1) * KC * 64, tid, bt0);
        gemm_chunk(As[buf], Bs[buf], tx, ty, acc);
        buf ^= 1;
    }

    // [t][hh][b] layout: 8 consecutive float4 stores per thread (fully coalesced)
    float4* gp = (float4*)(g_gPre + (size_t)t * HID * BATCH * 4);
#pragma unroll
    for (int v = 0; v < 8; v++) {
        int b = bt0 + ty * 8 + v;
        float4 o; o.x = acc[v][0]; o.y = acc[v][1]; o.z = acc[v][2]; o.w = acc[v][3];
        gp[(size_t)hh * BATCH + b] = o;
    }
}

// ---------------- dual-layer pipelined LSTM step ----------------
// Launch s: blocks with blockIdx.y < 16 run LAYER1 at t=s-1 (long, K=512) — first
// in linear block order so wave-1 starts the long work; blocks with
// blockIdx.y >= 16 run LAYER0 at t=s (short, K=256, seeded from gPre).
// Independence: layer0(s) writes g_hT[0][1-(s&1)]; layer1(s-1) reads g_hT[0][s&1].
__global__ void __launch_bounds__(256, 2)
lstm_dual_step(int s) {
    __shared__ __align__(16) float As[2][KC][BT];
    __shared__ __align__(16) float Bs[2][KC][64];

    const int layer = (blockIdx.y < NHT) ? 1 : 0;   // longs first in block order
    const int t = (layer == 0) ? s : (s - 1);
    if (layer == 0 && t >= TT) return;
    if (layer == 1 && t < 0) return;

    const int byi = blockIdx.y & (NHT - 1);
    const int tid = threadIdx.x;
    const int tx  = tid & 15;
    const int ty  = tid >> 4;
    const int bt0 = blockIdx.x * BT;
    const int p = t & 1;
    const int q = 1 - p;

    const float* a1 = (layer == 0) ? nullptr : g_hT[0][q];   // layer1: h0 at same t
    const float* a2 = g_hT[layer][p];                        // own h at t-1
    // layer0 uses only the w_hh half (k in [256,512)) of its packed weights
    const float* wsrc = g_wP[layer] + (size_t)byi * KTOT * 64
                        + (layer == 0 ? (size_t)HID * 64 : 0);

    const int hh = byi * NHT + tx;
    float acc[8][4];
    if (layer == 0) {
        // [t][hh][b] layout: 8 consecutive float4 loads per thread (coalesced)
        const float4* gp = (const float4*)(g_gPre + (size_t)t * HID * BATCH * 4);
#pragma unroll
        for (int v = 0; v < 8; v++) {
            int b = bt0 + ty * 8 + v;
            float4 g4 = gp[(size_t)hh * BATCH + b];
            acc[v][0] = g4.x; acc[v][1] = g4.y; acc[v][2] = g4.z; acc[v][3] = g4.w;
        }
    } else {
#pragma unroll
        for (int v = 0; v < 8; v++) {
            acc[v][0] = g_bC[1][0 * HID + hh];
            acc[v][1] = g_bC[1][1 * HID + hh];
            acc[v][2] = g_bC[1][2 * HID + hh];
            acc[v][3] = g_bC[1][3 * HID + hh];
        }
    }

    const int NCH = (layer == 0) ? (HID / KC) : (KTOT / KC);   // 8 or 16

    auto asrc_of = [&](int c) -> const float* {
        int kb = c * KC;
        if (layer == 0) return a2 + (size_t)kb * BATCH;
        return (kb < HID) ? (a1 + (size_t)kb * BATCH) : (a2 + (size_t)(kb - HID) * BATCH);
    };

    prefetch_tiles(As[0], Bs[0], asrc_of(0), wsrc, tid, bt0);
    int buf = 0;
    for (int c = 0; c < NCH; c++) {
        CP_WAIT0();
        __syncthreads();
        if (c + 1 < NCH)
            prefetch_tiles(As[buf ^ 1], Bs[buf ^ 1], asrc_of(c + 1),
                           wsrc + (size_t)(c + 1) * KC * 64, tid, bt0);
        gemm_chunk(As[buf], Bs[buf], tx, ty, acc);
        buf ^= 1;
    }

    // ---- LSTM cell epilogue: c is [h][b] like h -> fully vectorized I/O ----
    const int base = hh * BATCH + bt0 + ty * 8;          // 8 consecutive floats
    float* crow = &g_c[layer][0] + base;
    float* hout = &g_hT[layer][q][0] + base;

    float c_old[8], cn[8], hn[8];
    *(float4*)&c_old[0] = *(const float4*)&crow[0];      // 2x LDG.128
    *(float4*)&c_old[4] = *(const float4*)&crow[4];
#pragma unroll
    for (int v = 0; v < 8; v++) {
        float iv = sigmoidf_(acc[v][0]);
        float fv = sigmoidf_(acc[v][1]);
        float gv = tanhf(acc[v][2]);
        float ov = sigmoidf_(acc[v][3]);
        cn[v] = fv * c_old[v] + iv * gv;
        hn[v] = ov * tanhf(cn[v]);
    }
    *(float4*)&crow[0] = *(const float4*)&cn[0];         // 4x STG.128
    *(float4*)&crow[4] = *(const float4*)&cn[4];
    *(float4*)&hout[0] = *(const float4*)&hn[0];
    *(float4*)&hout[4] = *(const float4*)&hn[4];
}

// ---------------- FC head: out[b] = sigmoid(fc2 . relu(fc1 @ h + b1) + b2) ----------------
__global__ void fc_kernel(const float* __restrict__ fc1_w,
                          const float* __restrict__ fc1_b,
                          const float* __restrict__ fc2_w,
                          const float* __restrict__ fc2_b,
                          float* __restrict__ out) {
    __shared__ float hbuf[HID];
    __shared__ float red[4];
    int b = blockIdx.x;
    int tid = threadIdx.x;
    int lane = tid & 31, wid = tid >> 5;
    // final h of layer 1 is in parity buffer 0 (q = 1 - (127 & 1) = 0), layout [h][b]
    hbuf[tid]       = g_hT[1][0][(size_t)tid * BATCH + b];
    hbuf[tid + 128] = g_hT[1][0][(size_t)(tid + 128) * BATCH + b];
    __syncthreads();
    const float* wr = fc1_w + (size_t)tid * HID;
    float dot = 0.0f;
#pragma unroll 8
    for (int k = 0; k < HID; k++) dot += wr[k] * hbuf[k];
    float v = fmaxf(dot + fc1_b[tid], 0.0f) * fc2_w[tid];
#pragma unroll
    for (int o = 16; o > 0; o >>= 1) v += __shfl_down_sync(0xFFFFFFFFu, v, o);
    if (lane == 0) red[wid] = v;
    __syncthreads();
    if (tid == 0) {
        float sum = red[0] + red[1] + red[2] + red[3];
        out[b] = 1.0f / (1.0f + expf(-(sum + fc2_b[0])));
    }
}

extern "C" void kernel_launch(void* const* d_in, const int* in_sizes, int n_in,
                              void* d_out, int out_size) {
    const float* x     = (const float*)d_in[0];
    const float* w_ih0 = (const float*)d_in[1];
    const float* w_hh0 = (const float*)d_in[2];
    const float* b_ih0 = (const float*)d_in[3];
    const float* b_hh0 = (const float*)d_in[4];
    const float* w_ih1 = (const float*)d_in[5];
    const float* w_hh1 = (const float*)d_in[6];
    const float* b_ih1 = (const float*)d_in[7];
    const float* b_hh1 = (const float*)d_in[8];
    const float* fc1_w = (const float*)d_in[9];
    const float* fc1_b = (const float*)d_in[10];
    const float* fc2_w = (const float*)d_in[11];
    const float* fc2_b = (const float*)d_in[12];
    float* out = (float*)d_out;

    init_states_kernel<<<(BATCH * HID + 255) / 256, 256>>>();

    dim3 xgrid(BATCH / 32, HID / 32, TT);
    prep_x_kernel<<<xgrid, dim3(32, 8)>>>(x);

    int wtot = NHT * KTOT * 64;
    prep_w_kernel<<<(wtot + 255) / 256, 256>>>(w_ih0, w_hh0, b_ih0, b_hh0, 0);
    prep_w_kernel<<<(wtot + 255) / 256, 256>>>(w_ih1, w_hh1, b_ih1, b_hh1, 1);

    // hoisted input GEMM: all T at once, fully parallel (16384 blocks)
    dim3 pgrid(BATCH / BT, HID / NHT, TT);
    precompute_gates<<<pgrid, 256>>>();

    // pipelined sequential region: launch s computes layer1(s-1) || layer0(s)
    dim3 dgrid(BATCH / BT, 2 * (HID / NHT));   // 8 x 32 = 256 blocks
    for (int s = 0; s <= TT; s++) {
        lstm_dual_step<<<dgrid, 256>>>(s);
    }

    fc_kernel<<<BATCH, 128>>>(fc1_w, fc1_b, fc2_w, fc2_b, out);
}

// round 12
// speedup vs baseline: 1.0776x; 1.0776x over previous
#include <cuda_runtime.h>
#include <math.h>

#define BATCH 1024
#define TT    128
#define HID   256
#define KTOT  512      // [x|h] concat K (layer-1 path)
#define KC    32       // K chunk in SMEM
#define BT    128      // batch tile per block
#define NHT   16       // h indices per block (=> 64 gate cols, gate-minor)

typedef unsigned long long ull;

// ---------------- persistent device scratch (allocation-free) ----------------
__device__ __align__(16) float g_xT[(size_t)TT * HID * BATCH];   // [t][k][b], relu applied
__device__ __align__(16) float g_hT[2][2][HID * BATCH];          // [layer][parity][h][b]
__device__ __align__(16) float g_c[2][HID * BATCH];              // [layer][h][b]  (k-major like h)
__device__ __align__(16) float g_wP[2][(size_t)NHT * KTOT * 64]; // [layer][ht][k][col], col=jj*4+g
__device__ __align__(16) float g_bC[2][4 * HID];                 // combined bias [g][h]
__device__ __align__(16) float g_gPre[(size_t)TT * HID * BATCH * 4]; // [t][hh][b][4gates], bias folded

__device__ __forceinline__ float sigmoidf_(float v) { return 1.0f / (1.0f + expf(-v)); }

// ---- packed fp32x2 helpers (sm_103a FFMA2 path; per-lane exact IEEE fp32) ----
__device__ __forceinline__ ull pack2(float lo, float hi) {
    ull r; unsigned a = __float_as_uint(lo), b = __float_as_uint(hi);
    asm("mov.b64 %0, {%1, %2};" : "=l"(r) : "r"(a), "r"(b));
    return r;
}
__device__ __forceinline__ ull dup2(float v) {
    ull r; unsigned a = __float_as_uint(v);
    asm("mov.b64 %0, {%1, %2};" : "=l"(r) : "r"(a), "r"(a));
    return r;
}
__device__ __forceinline__ void unpack2(ull p, float& lo, float& hi) {
    unsigned a, b;
    asm("mov.b64 {%0, %1}, %2;" : "=r"(a), "=r"(b) : "l"(p));
    lo = __uint_as_float(a); hi = __uint_as_float(b);
}
#define FMA2(d, a, b) asm("fma.rn.f32x2 %0, %1, %2, %0;" : "+l"(d) : "l"(a), "l"(b))

__device__ __forceinline__ void cp_async16(void* smem_dst, const void* gsrc) {
    unsigned sa = (unsigned)__cvta_generic_to_shared(smem_dst);
    asm volatile("cp.async.cg.shared.global [%0], [%1], 16;\n" :: "r"(sa), "l"(gsrc));
}
#define CP_COMMIT() asm volatile("cp.async.commit_group;\n" ::: "memory")
#define CP_WAIT0()  asm volatile("cp.async.wait_group 0;\n" ::: "memory")

// ---------------- prep kernels (run inside the graph every replay) ----------------
__global__ void init_states_kernel() {
    int i = blockIdx.x * blockDim.x + threadIdx.x;
    if (i < BATCH * HID) {
        g_hT[0][0][i] = 0.0f; g_hT[0][1][i] = 0.0f;
        g_hT[1][0][i] = 0.0f; g_hT[1][1][i] = 0.0f;
        g_c[0][i] = 0.0f;     g_c[1][i] = 0.0f;
    }
}

// xT[t][k][b] = relu(x[b][t][k])
__global__ void prep_x_kernel(const float* __restrict__ x) {
    __shared__ float tile[32][33];
    int t  = blockIdx.z;
    int b0 = blockIdx.x * 32;
    int k0 = blockIdx.y * 32;
    int tx = threadIdx.x, ty = threadIdx.y;          // (32, 8)
#pragma unroll
    for (int r = ty; r < 32; r += 8)
        tile[r][tx] = fmaxf(x[((size_t)(b0 + r) * TT + t) * HID + k0 + tx], 0.0f);
    __syncthreads();
#pragma unroll
    for (int r = ty; r < 32; r += 8)
        g_xT[((size_t)t * HID + k0 + r) * BATCH + b0 + tx] = tile[tx][r];
}

// wP[ht][k][col] with col = jj*4 + g,  j = g*HID + ht*16 + jj;  k<256 -> w_ih else w_hh
__global__ void prep_w_kernel(const float* __restrict__ w_ih,
                              const float* __restrict__ w_hh,
                              const float* __restrict__ b_ih,
                              const float* __restrict__ b_hh,
                              int layer) {
    int idx = blockIdx.x * blockDim.x + threadIdx.x;     // [0, 16*512*64)
    if (idx < NHT * KTOT * 64) {
        int col = idx & 63;
        int k   = (idx >> 6) & (KTOT - 1);
        int ht  = idx >> 15;
        int g   = col & 3;
        int jj  = col >> 2;
        int j   = g * HID + ht * 16 + jj;
        float v = (k < HID) ? w_ih[(size_t)j * HID + k] : w_hh[(size_t)j * HID + (k - HID)];
        g_wP[layer][idx] = v;
    }
    if (idx < 4 * HID) g_bC[layer][idx] = b_ih[idx] + b_hh[idx];
}

// ---------------- shared GEMM tile machinery (packed f32x2 accumulators) ----------------
// Block tile: 128 batches x 16 h-indices (64 gate cols, gate-minor). 256 threads.
// Thread (tx, ty): tx = h-index-local [0,16), ty = batch group [0,16) of 8 rows.
// accp[u][g] = packed pair (batch v=2u, v=2u+1) of gate g. 16 x 64-bit = 32 regs.
__device__ __forceinline__ void gemm_chunk(const float As[KC][BT], const float Bs[KC][64],
                                           int tx, int ty, ull accp[4][4]) {
#pragma unroll 8
    for (int kk = 0; kk < KC; kk++) {
        // a pairs load directly as 64-bit lanes (adjacent batches), broadcast across tx
        ulonglong2 a01 = *(const ulonglong2*)&As[kk][ty * 8];      // (v0,v1), (v2,v3)
        ulonglong2 a23 = *(const ulonglong2*)&As[kk][ty * 8 + 4];  // (v4,v5), (v6,v7)
        float4 b = *(const float4*)&Bs[kk][tx * 4];                // 4 gates of one jj
        ull b0 = dup2(b.x), b1 = dup2(b.y), b2 = dup2(b.z), b3 = dup2(b.w);
        FMA2(accp[0][0], a01.x, b0); FMA2(accp[0][1], a01.x, b1);
        FMA2(accp[0][2], a01.x, b2); FMA2(accp[0][3], a01.x, b3);
        FMA2(accp[1][0], a01.y, b0); FMA2(accp[1][1], a01.y, b1);
        FMA2(accp[1][2], a01.y, b2); FMA2(accp[1][3], a01.y, b3);
        FMA2(accp[2][0], a23.x, b0); FMA2(accp[2][1], a23.x, b1);
        FMA2(accp[2][2], a23.x, b2); FMA2(accp[2][3], a23.x, b3);
        FMA2(accp[3][0], a23.y, b0); FMA2(accp[3][1], a23.y, b1);
        FMA2(accp[3][2], a23.y, b2); FMA2(accp[3][3], a23.y, b3);
    }
}

__device__ __forceinline__ void prefetch_tiles(float As[KC][BT], float Bs[KC][64],
                                               const float* asrc, const float* wsrc_c,
                                               int tid, int bt0) {
#pragma unroll
    for (int s = 0; s < 4; s++) {              // A: 32x128 = 1024 float4
        int idx = tid + s * 256;
        int k = idx >> 5, f = idx & 31;
        cp_async16(&As[k][f * 4], asrc + (size_t)k * BATCH + bt0 + f * 4);
    }
#pragma unroll
    for (int s = 0; s < 2; s++) {              // B: 32x64 = 512 float4
        int idx = tid + s * 256;
        int k = idx >> 4, f = idx & 15;
        cp_async16(&Bs[k][f * 4], wsrc_c + (size_t)k * 64 + f * 4);
    }
    CP_COMMIT();
}

// ---------------- parallel input GEMM: gPre[t][hh][b][g] = relu(x)@W_ih0^T + bias0 ----------------
__global__ void __launch_bounds__(256, 2)
precompute_gates() {
    __shared__ __align__(16) float As[2][KC][BT];
    __shared__ __align__(16) float Bs[2][KC][64];

    const int tid = threadIdx.x;
    const int tx  = tid & 15;
    const int ty  = tid >> 4;
    const int bt0 = blockIdx.x * BT;
    const int t   = blockIdx.z;
    const float* a1   = g_xT + (size_t)t * HID * BATCH;
    const float* wsrc = g_wP[0] + (size_t)blockIdx.y * KTOT * 64;   // k in [0,256): w_ih part

    const int hh = blockIdx.y * NHT + tx;
    ull accp[4][4];
#pragma unroll
    for (int u = 0; u < 4; u++) {
        accp[u][0] = dup2(g_bC[0][0 * HID + hh]);
        accp[u][1] = dup2(g_bC[0][1 * HID + hh]);
        accp[u][2] = dup2(g_bC[0][2 * HID + hh]);
        accp[u][3] = dup2(g_bC[0][3 * HID + hh]);
    }

    const int NCH = HID / KC;   // 8 chunks, input half only
    prefetch_tiles(As[0], Bs[0], a1, wsrc, tid, bt0);
    int buf = 0;
    for (int c = 0; c < NCH; c++) {
        CP_WAIT0();
        __syncthreads();
        if (c + 1 < NCH)
            prefetch_tiles(As[buf ^ 1], Bs[buf ^ 1],
                           a1 + (size_t)(c + 1) * KC * BATCH,
                           wsrc + (size_t)(c + 1) * KC * 64, tid, bt0);
        gemm_chunk(As[buf], Bs[buf], tx, ty, accp);
        buf ^= 1;
    }

    // [t][hh][b] layout: 8 consecutive float4 stores per thread (fully coalesced)
    float4* gp = (float4*)(g_gPre + (size_t)t * HID * BATCH * 4);
#pragma unroll
    for (int u = 0; u < 4; u++) {
        float4 oa, ob;
        unpack2(accp[u][0], oa.x, ob.x);
        unpack2(accp[u][1], oa.y, ob.y);
        unpack2(accp[u][2], oa.z, ob.z);
        unpack2(accp[u][3], oa.w, ob.w);
        int b = bt0 + ty * 8 + 2 * u;
        gp[(size_t)hh * BATCH + b]     = oa;
        gp[(size_t)hh * BATCH + b + 1] = ob;
    }
}

// ---------------- dual-layer pipelined LSTM step ----------------
// Launch s: blocks with blockIdx.y < 16 run LAYER1 at t=s-1 (long, K=512) — first
// in linear block order so wave-1 starts the long work; blocks with
// blockIdx.y >= 16 run LAYER0 at t=s (short, K=256, seeded from gPre).
// Independence: layer0(s) writes g_hT[0][1-(s&1)]; layer1(s-1) reads g_hT[0][s&1].
__global__ void __launch_bounds__(256, 2)
lstm_dual_step(int s) {
    __shared__ __align__(16) float As[2][KC][BT];
    __shared__ __align__(16) float Bs[2][KC][64];

    const int layer = (blockIdx.y < NHT) ? 1 : 0;   // longs first in block order
    const int t = (layer == 0) ? s : (s - 1);
    if (layer == 0 && t >= TT) return;
    if (layer == 1 && t < 0) return;

    const int byi = blockIdx.y & (NHT - 1);
    const int tid = threadIdx.x;
    const int tx  = tid & 15;
    const int ty  = tid >> 4;
    const int bt0 = blockIdx.x * BT;
    const int p = t & 1;
    const int q = 1 - p;

    const float* a1 = (layer == 0) ? nullptr : g_hT[0][q];   // layer1: h0 at same t
    const float* a2 = g_hT[layer][p];                        // own h at t-1
    // layer0 uses only the w_hh half (k in [256,512)) of its packed weights
    const float* wsrc = g_wP[layer] + (size_t)byi * KTOT * 64
                        + (layer == 0 ? (size_t)HID * 64 : 0);

    const int hh = byi * NHT + tx;
    ull accp[4][4];
    if (layer == 0) {
        // [t][hh][b] layout: consecutive float4 loads per thread (coalesced)
        const float4* gp = (const float4*)(g_gPre + (size_t)t * HID * BATCH * 4);
#pragma unroll
        for (int u = 0; u < 4; u++) {
            int b = bt0 + ty * 8 + 2 * u;
            float4 ga = gp[(size_t)hh * BATCH + b];
            float4 gb = gp[(size_t)hh * BATCH + b + 1];
            accp[u][0] = pack2(ga.x, gb.x);
            accp[u][1] = pack2(ga.y, gb.y);
            accp[u][2] = pack2(ga.z, gb.z);
            accp[u][3] = pack2(ga.w, gb.w);
        }
    } else {
#pragma unroll
        for (int u = 0; u < 4; u++) {
            accp[u][0] = dup2(g_bC[1][0 * HID + hh]);
            accp[u][1] = dup2(g_bC[1][1 * HID + hh]);
            accp[u][2] = dup2(g_bC[1][2 * HID + hh]);
            accp[u][3] = dup2(g_bC[1][3 * HID + hh]);
        }
    }

    const int NCH = (layer == 0) ? (HID / KC) : (KTOT / KC);   // 8 or 16

    auto asrc_of = [&](int c) -> const float* {
        int kb = c * KC;
        if (layer == 0) return a2 + (size_t)kb * BATCH;
        return (kb < HID) ? (a1 + (size_t)kb * BATCH) : (a2 + (size_t)(kb - HID) * BATCH);
    };

    prefetch_tiles(As[0], Bs[0], asrc_of(0), wsrc, tid, bt0);
    int buf = 0;
    for (int c = 0; c < NCH; c++) {
        CP_WAIT0();
        __syncthreads();
        if (c + 1 < NCH)
            prefetch_tiles(As[buf ^ 1], Bs[buf ^ 1], asrc_of(c + 1),
                           wsrc + (size_t)(c + 1) * KC * 64, tid, bt0);
        gemm_chunk(As[buf], Bs[buf], tx, ty, accp);
        buf ^= 1;
    }

    // ---- LSTM cell epilogue: unpack pairs, c is [h][b] -> fully vectorized I/O ----
    float acc[8][4];
#pragma unroll
    for (int u = 0; u < 4; u++) {
#pragma unroll
        for (int g = 0; g < 4; g++)
            unpack2(accp[u][g], acc[2 * u][g], acc[2 * u + 1][g]);
    }

    const int base = hh * BATCH + bt0 + ty * 8;          // 8 consecutive floats
    float* crow = &g_c[layer][0] + base;
    float* hout = &g_hT[layer][q][0] + base;

    float c_old[8], cn[8], hn[8];
    *(float4*)&c_old[0] = *(const float4*)&crow[0];      // 2x LDG.128
    *(float4*)&c_old[4] = *(const float4*)&crow[4];
#pragma unroll
    for (int v = 0; v < 8; v++) {
        float iv = sigmoidf_(acc[v][0]);
        float fv = sigmoidf_(acc[v][1]);
        float gv = tanhf(acc[v][2]);
        float ov = sigmoidf_(acc[v][3]);
        cn[v] = fv * c_old[v] + iv * gv;
        hn[v] = ov * tanhf(cn[v]);
    }
    *(float4*)&crow[0] = *(const float4*)&cn[0];         // 4x STG.128
    *(float4*)&crow[4] = *(const float4*)&cn[4];
    *(float4*)&hout[0] = *(const float4*)&hn[0];
    *(float4*)&hout[4] = *(const float4*)&hn[4];
}

// ---------------- FC head: out[b] = sigmoid(fc2 . relu(fc1 @ h + b1) + b2) ----------------
__global__ void fc_kernel(const float* __restrict__ fc1_w,
                          const float* __restrict__ fc1_b,
                          const float* __restrict__ fc2_w,
                          const float* __restrict__ fc2_b,
                          float* __restrict__ out) {
    __shared__ float hbuf[HID];
    __shared__ float red[4];
    int b = blockIdx.x;
    int tid = threadIdx.x;
    int lane = tid & 31, wid = tid >> 5;
    // final h of layer 1 is in parity buffer 0 (q = 1 - (127 & 1) = 0), layout [h][b]
    hbuf[tid]       = g_hT[1][0][(size_t)tid * BATCH + b];
    hbuf[tid + 128] = g_hT[1][0][(size_t)(tid + 128) * BATCH + b];
    __syncthreads();
    const float* wr = fc1_w + (size_t)tid * HID;
    float dot = 0.0f;
#pragma unroll 8
    for (int k = 0; k < HID; k++) dot += wr[k] * hbuf[k];
    float v = fmaxf(dot + fc1_b[tid], 0.0f) * fc2_w[tid];
#pragma unroll
    for (int o = 16; o > 0; o >>= 1) v += __shfl_down_sync(0xFFFFFFFFu, v, o);
    if (lane == 0) red[wid] = v;
    __syncthreads();
    if (tid == 0) {
        float sum = red[0] + red[1] + red[2] + red[3];
        out[b] = 1.0f / (1.0f + expf(-(sum + fc2_b[0])));
    }
}

extern "C" void kernel_launch(void* const* d_in, const int* in_sizes, int n_in,
                              void* d_out, int out_size) {
    const float* x     = (const float*)d_in[0];
    const float* w_ih0 = (const float*)d_in[1];
    const float* w_hh0 = (const float*)d_in[2];
    const float* b_ih0 = (const float*)d_in[3];
    const float* b_hh0 = (const float*)d_in[4];
    const float* w_ih1 = (const float*)d_in[5];
    const float* w_hh1 = (const float*)d_in[6];
    const float* b_ih1 = (const float*)d_in[7];
    const float* b_hh1 = (const float*)d_in[8];
    const float* fc1_w = (const float*)d_in[9];
    const float* fc1_b = (const float*)d_in[10];
    const float* fc2_w = (const float*)d_in[11];
    const float* fc2_b = (const float*)d_in[12];
    float* out = (float*)d_out;

    init_states_kernel<<<(BATCH * HID + 255) / 256, 256>>>();

    dim3 xgrid(BATCH / 32, HID / 32, TT);
    prep_x_kernel<<<xgrid, dim3(32, 8)>>>(x);

    int wtot = NHT * KTOT * 64;
    prep_w_kernel<<<(wtot + 255) / 256, 256>>>(w_ih0, w_hh0, b_ih0, b_hh0, 0);
    prep_w_kernel<<<(wtot + 255) / 256, 256>>>(w_ih1, w_hh1, b_ih1, b_hh1, 1);

    // hoisted input GEMM: all T at once, fully parallel (16384 blocks)
    dim3 pgrid(BATCH / BT, HID / NHT, TT);
    precompute_gates<<<pgrid, 256>>>();

    // pipelined sequential region: launch s computes layer1(s-1) || layer0(s)
    dim3 dgrid(BATCH / BT, 2 * (HID / NHT));   // 8 x 32 = 256 blocks
    for (int s = 0; s <= TT; s++) {
        lstm_dual_step<<<dgrid, 256>>>(s);
    }

    fc_kernel<<<BATCH, 128>>>(fc1_w, fc1_b, fc2_w, fc2_b, out);
}